// round 12
// baseline (speedup 1.0000x reference)
#include <cuda_runtime.h>
#include <cuda_fp16.h>
#include <cstdint>
#include <cstddef>

#define BATCH  65536
#define TILE_M 64
#define AS     272            // smem row stride (17*16): conflict-free ldmatrix phases
#define SM_BUFA 0
#define SM_BUFB 17408         // 64*272
#define SM_BIAS 34816         // b0[384] f32 then b1[384] f32
#define SMEM_TOTAL 37888

// ---------------- pre-packed fp16 B fragments ----------------
// Layer tables: nt-PAIRED records. uint4 record at
//   idx4 = (( (ntg>>1)*KT + kt )*32 + lane)   (scaled by 4 uint32)
// holds {b0,b1}(ntg even), {b0,b1}(ntg odd) -> one LDG.128 feeds 2 mmas.
__device__ uint32_t g_B0[48 * 4 * 32 * 2];     // layer0: 48 ntiles, KT=4 (K=64)
__device__ uint32_t g_B1[48 * 8 * 32 * 2];     // layer1: 48 ntiles, KT=8 (K=128)
__device__ uint32_t g_B2[3 * 8 * 32 * 2];      // heads : 3 ntiles (N=24), unpaired uint2
__device__ float g_b0[384], g_b1[384];         // folded biases, gate-major (i,g,o)

__device__ __forceinline__ uint32_t hpack(float w0, float w1) {
    __half2 h = __floats2half2_rn(w0, w1);
    return *(uint32_t*)&h;
}

__global__ void prep_kernel(const float* __restrict__ Wih0,
                            const float* __restrict__ bih0, const float* __restrict__ bhh0,
                            const float* __restrict__ Wih1,
                            const float* __restrict__ bih1, const float* __restrict__ bhh1,
                            const float* __restrict__ Wp,   const float* __restrict__ Wv)
{
    int t = blockIdx.x * blockDim.x + threadIdx.x;
    int NT = gridDim.x * blockDim.x;
    // gate source row bases: i=0, g=256, o=384 (f dead: h=c=0)
    for (int e = t; e < 48 * 4 * 32; e += NT) {          // layer0, K=64, KT=4
        int lane = e & 31, kt = (e >> 5) & 3, ntg = e >> 7;
        int col = (ntg << 3) + (lane >> 2);
        int gate = col >> 7, j = col & 127;
        int srcR = ((gate == 1) ? 256 : (gate == 2) ? 384 : 0) + j;
        const float* Wr = Wih0 + (size_t)srcR * 64;
        int ks = kt * 16 + ((lane & 3) << 1);
        #pragma unroll
        for (int r = 0; r < 2; r++) {
            int k = ks + (r << 3);
            g_B0[((((ntg >> 1) << 2) + kt) * 32 + lane) * 4 + ((ntg & 1) << 1) + r]
                = hpack(Wr[k], Wr[k + 1]);
        }
    }
    for (int e = t; e < 48 * 8 * 32; e += NT) {          // layer1, K=128, KT=8
        int lane = e & 31, kt = (e >> 5) & 7, ntg = e >> 8;
        int col = (ntg << 3) + (lane >> 2);
        int gate = col >> 7, j = col & 127;
        int srcR = ((gate == 1) ? 256 : (gate == 2) ? 384 : 0) + j;
        const float* Wr = Wih1 + (size_t)srcR * 128;
        int ks = kt * 16 + ((lane & 3) << 1);
        #pragma unroll
        for (int r = 0; r < 2; r++) {
            int k = ks + (r << 3);
            g_B1[((((ntg >> 1) << 3) + kt) * 32 + lane) * 4 + ((ntg & 1) << 1) + r]
                = hpack(Wr[k], Wr[k + 1]);
        }
    }
    for (int e = t; e < 3 * 8 * 32; e += NT) {           // heads: rows 0-15 Wp, 16 Wv, rest 0
        int lane = e & 31, kt = (e >> 5) & 7, nt = e >> 8;
        int col = (nt << 3) + (lane >> 2);
        int ks = kt * 16 + ((lane & 3) << 1);
        #pragma unroll
        for (int r = 0; r < 2; r++) {
            int k = ks + (r << 3);
            float w0 = (col < 16) ? Wp[(size_t)col * 128 + k]     : ((col == 16) ? Wv[k]     : 0.0f);
            float w1 = (col < 16) ? Wp[(size_t)col * 128 + k + 1] : ((col == 16) ? Wv[k + 1] : 0.0f);
            g_B2[(((nt << 3) + kt) * 32 + lane) * 2 + r] = hpack(w0, w1);
        }
    }
    for (int i = t; i < 384; i += NT) {
        int gate = i >> 7, j = i & 127;
        int R = ((gate == 1) ? 256 : (gate == 2) ? 384 : 0) + j;
        g_b0[i] = bih0[R] + bhh0[R];
        g_b1[i] = bih1[R] + bhh1[R];
    }
}

// ---------------- mma / activation helpers ----------------
__device__ __forceinline__ uint32_t smem_u32(const void* p) {
    uint32_t a;
    asm("{ .reg .u64 t; cvta.to.shared.u64 t, %1; cvt.u32.u64 %0, t; }" : "=r"(a) : "l"(p));
    return a;
}
__device__ __forceinline__ void ldmx4(uint32_t* r, uint32_t a) {
    asm volatile("ldmatrix.sync.aligned.m8n8.x4.shared.b16 {%0,%1,%2,%3}, [%4];"
                 : "=r"(r[0]), "=r"(r[1]), "=r"(r[2]), "=r"(r[3]) : "r"(a));
}
__device__ __forceinline__ void mma16816(float* c, const uint32_t* a, uint32_t b0, uint32_t b1) {
    asm volatile("mma.sync.aligned.m16n8k16.row.col.f32.f16.f16.f32 "
                 "{%0,%1,%2,%3}, {%4,%5,%6,%7}, {%8,%9}, {%0,%1,%2,%3};"
                 : "+f"(c[0]), "+f"(c[1]), "+f"(c[2]), "+f"(c[3])
                 : "r"(a[0]), "r"(a[1]), "r"(a[2]), "r"(a[3]), "r"(b0), "r"(b1));
}
__device__ __forceinline__ __half2 htanh2(__half2 v) {
    uint32_t r, xin = *(uint32_t*)&v;
    asm("tanh.approx.f16x2 %0, %1;" : "=r"(r) : "r"(xin));
    return *(__half2*)&r;
}

// ---------------- one LSTM layer: fp16 GEMM + f16x2 activation ----------------
template <int KT>
__device__ __forceinline__ void gemm_layer(char* smem, uint32_t sbase,
                                           int aOff, int hOff,
                                           const uint32_t* __restrict__ Bf,
                                           const float* __restrict__ bias,  // smem ptr
                                           int m0, int lane, int jhalf)
{
    const __half2 H05 = __floats2half2_rn(0.5f, 0.5f);
    #pragma unroll
    for (int jci = 0; jci < 2; jci++) {
        int jc = 2 * jhalf + jci;
        float acc[3][4][4];
        #pragma unroll
        for (int z = 0; z < 48; z++) ((float*)acc)[z] = 0.0f;

        #pragma unroll
        for (int kt = 0; kt < KT; kt++) {
            uint32_t Ah[4];
            uint32_t a = sbase + (uint32_t)aOff
                       + (uint32_t)(m0 + (lane & 15)) * AS
                       + (uint32_t)(kt * 32 + (lane >> 4) * 16);
            ldmx4(Ah, a);
            #pragma unroll
            for (int g = 0; g < 3; g++)
                #pragma unroll
                for (int ntp = 0; ntp < 2; ntp++) {
                    // paired record: pairIdx = (g<<3) + (jc<<1) + ntp
                    int pairIdx = (g << 3) + (jc << 1) + ntp;
                    uint4 b4 = *(const uint4*)&Bf[((pairIdx * KT + kt) * 32 + lane) * 4];
                    mma16816(acc[g][2 * ntp],     Ah, b4.x, b4.y);
                    mma16816(acc[g][2 * ntp + 1], Ah, b4.z, b4.w);
                }
        }
        // epilogue: f16x2 activations (sigma(z) = 0.5 + 0.5*tanh(z/2); f*c = 0)
        #pragma unroll
        for (int nt = 0; nt < 4; nt++)
            #pragma unroll
            for (int i2 = 0; i2 < 2; i2++) {
                int jb = (jc << 5) + (nt << 3) + ((lane & 3) << 1);
                float ai0 = acc[0][nt][2 * i2]     + bias[jb];
                float ai1 = acc[0][nt][2 * i2 + 1] + bias[jb + 1];
                float ag0 = acc[1][nt][2 * i2]     + bias[128 + jb];
                float ag1 = acc[1][nt][2 * i2 + 1] + bias[128 + jb + 1];
                float ao0 = acc[2][nt][2 * i2]     + bias[256 + jb];
                float ao1 = acc[2][nt][2 * i2 + 1] + bias[256 + jb + 1];
                __half2 si = __hfma2(htanh2(__floats2half2_rn(0.5f * ai0, 0.5f * ai1)), H05, H05);
                __half2 gg = htanh2(__floats2half2_rn(ag0, ag1));
                __half2 so = __hfma2(htanh2(__floats2half2_rn(0.5f * ao0, 0.5f * ao1)), H05, H05);
                __half2 tc = htanh2(__hmul2(si, gg));
                __half2 h2 = __hmul2(so, tc);
                int row = m0 + (lane >> 2) + (i2 << 3);
                *(uint32_t*)(smem + hOff + row * AS + jb * 2) = *(uint32_t*)&h2;
            }
    }
}

__global__ void __launch_bounds__(256, 2)
lstm_mma_kernel(const float* __restrict__ x,
                const float* __restrict__ bp, const float* __restrict__ bv,
                float* __restrict__ out)
{
    extern __shared__ char smem[];
    uint32_t sbase = smem_u32(smem);
    int tid = threadIdx.x;
    int lane = tid & 31;
    int warp = tid >> 5;
    int jhalf = warp & 1;            // N-column half owned by this warp
    int m0 = (warp >> 1) << 4;       // 16-row group
    int r0 = blockIdx.x * TILE_M;

    // ---- stage biases ----
    float* bias_s = (float*)(smem + SM_BIAS);
    for (int i = tid; i < 384; i += 256) { bias_s[i] = g_b0[i]; bias_s[384 + i] = g_b1[i]; }

    // ---- stage x as fp16 into bufA (128B per row) ----
    {
        const float4* xg = (const float4*)(x + (size_t)r0 * 64);
        for (int it = tid; it < 64 * 16; it += 256) {
            int r = it >> 4, c4 = it & 15;
            float4 v = xg[r * 16 + c4];
            char* p = smem + SM_BUFA + r * AS + (c4 << 3);
            *(uint32_t*)p       = hpack(v.x, v.y);
            *(uint32_t*)(p + 4) = hpack(v.z, v.w);
        }
    }
    __syncthreads();

    gemm_layer<4>(smem, sbase, SM_BUFA, SM_BUFB, g_B0, bias_s,       m0, lane, jhalf);  // x -> h0
    __syncthreads();
    gemm_layer<8>(smem, sbase, SM_BUFB, SM_BUFA, g_B1, bias_s + 384, m0, lane, jhalf);  // h0 -> h1
    __syncthreads();

    // ---- heads: h1 @ [Wp;Wv]^T, N=24. jhalf0: nt{0,2}, jhalf1: nt{1} ----
    {
        float acc[2][4];
        #pragma unroll
        for (int z = 0; z < 8; z++) ((float*)acc)[z] = 0.0f;
        int nt0 = jhalf ? 1 : 0;
        int nt1 = jhalf ? -1 : 2;    // second tile only for jhalf0

        #pragma unroll
        for (int kt = 0; kt < 8; kt++) {
            uint32_t Ah[4];
            uint32_t a = sbase + SM_BUFA
                       + (uint32_t)(m0 + (lane & 15)) * AS
                       + (uint32_t)(kt * 32 + (lane >> 4) * 16);
            ldmx4(Ah, a);
            {
                uint2 b = *(const uint2*)&g_B2[(((nt0 << 3) + kt) * 32 + lane) * 2];
                mma16816(acc[0], Ah, b.x, b.y);
            }
            if (nt1 >= 0) {
                uint2 b = *(const uint2*)&g_B2[(((nt1 << 3) + kt) * 32 + lane) * 2];
                mma16816(acc[1], Ah, b.x, b.y);
            }
        }
        float bv0 = __ldg(bv);
        #pragma unroll
        for (int i2 = 0; i2 < 2; i2++) {
            int row = r0 + m0 + (lane >> 2) + (i2 << 3);
            {   // policy tile nt0 (cols nt0*8 .. nt0*8+7)
                int j0 = (nt0 << 3) + ((lane & 3) << 1);
                float2 v;
                v.x = acc[0][2 * i2]     + __ldg(bp + j0);
                v.y = acc[0][2 * i2 + 1] + __ldg(bp + j0 + 1);
                *(float2*)(out + (size_t)row * 16 + j0) = v;
            }
            if (nt1 >= 0 && (lane & 3) == 0)   // value = col 16
                out[(size_t)BATCH * 16 + row] = acc[1][2 * i2] + bv0;
        }
    }
}

extern "C" void kernel_launch(void* const* d_in, const int* in_sizes, int n_in,
                              void* d_out, int out_size)
{
    (void)in_sizes; (void)n_in; (void)out_size;
    const float* x    = (const float*)d_in[0];
    const float* Wih0 = (const float*)d_in[1];
    const float* bih0 = (const float*)d_in[3];
    const float* bhh0 = (const float*)d_in[4];
    const float* Wih1 = (const float*)d_in[5];
    const float* bih1 = (const float*)d_in[7];
    const float* bhh1 = (const float*)d_in[8];
    const float* Wp   = (const float*)d_in[9];
    const float* bp   = (const float*)d_in[10];
    const float* Wv   = (const float*)d_in[11];
    const float* bv   = (const float*)d_in[12];
    float* out = (float*)d_out;

    prep_kernel<<<64, 256>>>(Wih0, bih0, bhh0, Wih1, bih1, bhh1, Wp, Wv);

    cudaFuncSetAttribute(lstm_mma_kernel,
                         cudaFuncAttributeMaxDynamicSharedMemorySize, SMEM_TOTAL);
    lstm_mma_kernel<<<BATCH / TILE_M, 256, SMEM_TOTAL>>>(x, bp, bv, out);
}

// round 16
// speedup vs baseline: 1.2257x; 1.2257x over previous
#include <cuda_runtime.h>
#include <cuda_fp16.h>
#include <cstdint>
#include <cstddef>

#define BATCH  65536
#define TILE_M 64
#define AS     272            // smem row stride (17*16): conflict-free ldmatrix phases
#define SM_BUFA 0
#define SM_BUFB 17408         // 64*272
#define SM_BIAS 34816         // b0[384] f32 then b1[384] f32
#define SMEM_TOTAL 37888

// ---------------- pre-packed fp16 B fragments (per-lane mma layout, uint2 records) ----------------
// entry: ((ntg*KT + kt)*32 + lane)*2 + reg
__device__ uint32_t g_B0[48 * 4 * 32 * 2];     // layer0: 48 ntiles, KT=4 (K=64)
__device__ uint32_t g_B1[48 * 8 * 32 * 2];     // layer1: 48 ntiles, KT=8 (K=128)
__device__ uint32_t g_B2[3 * 8 * 32 * 2];      // heads : 3 ntiles (N=24)
__device__ float g_b0[384], g_b1[384];         // folded biases, gate-major (i,g,o)

__device__ __forceinline__ uint32_t hpack(float w0, float w1) {
    __half2 h = __floats2half2_rn(w0, w1);
    return *(uint32_t*)&h;
}

__global__ void prep_kernel(const float* __restrict__ Wih0,
                            const float* __restrict__ bih0, const float* __restrict__ bhh0,
                            const float* __restrict__ Wih1,
                            const float* __restrict__ bih1, const float* __restrict__ bhh1,
                            const float* __restrict__ Wp,   const float* __restrict__ Wv)
{
    int t = blockIdx.x * blockDim.x + threadIdx.x;
    int NT = gridDim.x * blockDim.x;
    // gate source row bases: i=0, g=256, o=384 (f dead: h=c=0)
    for (int e = t; e < 48 * 4 * 32; e += NT) {          // layer0, K=64
        int lane = e & 31, kt = (e >> 5) & 3, nt = e >> 7;
        int col = (nt << 3) + (lane >> 2);
        int gate = col >> 7, j = col & 127;
        int srcR = ((gate == 1) ? 256 : (gate == 2) ? 384 : 0) + j;
        const float* Wr = Wih0 + (size_t)srcR * 64;
        int ks = kt * 16 + ((lane & 3) << 1);
        #pragma unroll
        for (int r = 0; r < 2; r++) {
            int k = ks + (r << 3);
            g_B0[(((nt << 2) + kt) * 32 + lane) * 2 + r] = hpack(Wr[k], Wr[k + 1]);
        }
    }
    for (int e = t; e < 48 * 8 * 32; e += NT) {          // layer1, K=128
        int lane = e & 31, kt = (e >> 5) & 7, nt = e >> 8;
        int col = (nt << 3) + (lane >> 2);
        int gate = col >> 7, j = col & 127;
        int srcR = ((gate == 1) ? 256 : (gate == 2) ? 384 : 0) + j;
        const float* Wr = Wih1 + (size_t)srcR * 128;
        int ks = kt * 16 + ((lane & 3) << 1);
        #pragma unroll
        for (int r = 0; r < 2; r++) {
            int k = ks + (r << 3);
            g_B1[(((nt << 3) + kt) * 32 + lane) * 2 + r] = hpack(Wr[k], Wr[k + 1]);
        }
    }
    for (int e = t; e < 3 * 8 * 32; e += NT) {           // heads: rows 0-15 Wp, 16 Wv, rest 0
        int lane = e & 31, kt = (e >> 5) & 7, nt = e >> 8;
        int col = (nt << 3) + (lane >> 2);
        int ks = kt * 16 + ((lane & 3) << 1);
        #pragma unroll
        for (int r = 0; r < 2; r++) {
            int k = ks + (r << 3);
            float w0 = (col < 16) ? Wp[(size_t)col * 128 + k]     : ((col == 16) ? Wv[k]     : 0.0f);
            float w1 = (col < 16) ? Wp[(size_t)col * 128 + k + 1] : ((col == 16) ? Wv[k + 1] : 0.0f);
            g_B2[(((nt << 3) + kt) * 32 + lane) * 2 + r] = hpack(w0, w1);
        }
    }
    for (int i = t; i < 384; i += NT) {
        int gate = i >> 7, j = i & 127;
        int R = ((gate == 1) ? 256 : (gate == 2) ? 384 : 0) + j;
        g_b0[i] = bih0[R] + bhh0[R];
        g_b1[i] = bih1[R] + bhh1[R];
    }
}

// ---------------- mma / activation helpers ----------------
__device__ __forceinline__ uint32_t smem_u32(const void* p) {
    uint32_t a;
    asm("{ .reg .u64 t; cvta.to.shared.u64 t, %1; cvt.u32.u64 %0, t; }" : "=r"(a) : "l"(p));
    return a;
}
__device__ __forceinline__ void ldmx4(uint32_t* r, uint32_t a) {
    asm volatile("ldmatrix.sync.aligned.m8n8.x4.shared.b16 {%0,%1,%2,%3}, [%4];"
                 : "=r"(r[0]), "=r"(r[1]), "=r"(r[2]), "=r"(r[3]) : "r"(a));
}
__device__ __forceinline__ void mma16816(float* c, const uint32_t* a, uint32_t b0, uint32_t b1) {
    asm volatile("mma.sync.aligned.m16n8k16.row.col.f32.f16.f16.f32 "
                 "{%0,%1,%2,%3}, {%4,%5,%6,%7}, {%8,%9}, {%0,%1,%2,%3};"
                 : "+f"(c[0]), "+f"(c[1]), "+f"(c[2]), "+f"(c[3])
                 : "r"(a[0]), "r"(a[1]), "r"(a[2]), "r"(a[3]), "r"(b0), "r"(b1));
}
__device__ __forceinline__ __half2 htanh2(__half2 v) {
    uint32_t r, xin = *(uint32_t*)&v;
    asm("tanh.approx.f16x2 %0, %1;" : "=r"(r) : "r"(xin));
    return *(__half2*)&r;
}

// ---------------- one LSTM layer: warp = 32 rows x 32 cols ----------------
// Inner jci halves (16 cols) keep acc at 2mt*3g*2nt*4 = 48 floats.
// 12 mmas per 6 B-LDG.64 per kt -> 2 mma per B load (B bytes halved vs 16-row warps).
template <int KT>
__device__ __forceinline__ void gemm_layer(char* smem, uint32_t sbase,
                                           int aOff, int hOff,
                                           const uint32_t* __restrict__ Bf,
                                           const float* __restrict__ bias,  // smem ptr
                                           int m0, int lane, int jq)
{
    const __half2 H05 = __floats2half2_rn(0.5f, 0.5f);
    #pragma unroll
    for (int jci = 0; jci < 2; jci++) {
        float acc[2][3][2][4];
        #pragma unroll
        for (int z = 0; z < 48; z++) ((float*)acc)[z] = 0.0f;

        #pragma unroll
        for (int kt = 0; kt < KT; kt++) {
            uint32_t Ah[2][4];
            #pragma unroll
            for (int mt = 0; mt < 2; mt++) {
                uint32_t a = sbase + (uint32_t)aOff
                           + (uint32_t)(m0 + mt * 16 + (lane & 15)) * AS
                           + (uint32_t)(kt * 32 + (lane >> 4) * 16);
                ldmx4(Ah[mt], a);
            }
            #pragma unroll
            for (int g = 0; g < 3; g++)
                #pragma unroll
                for (int nt = 0; nt < 2; nt++) {
                    int ntg = (g << 4) + (jq << 2) + (jci << 1) + nt;
                    uint2 b = *(const uint2*)&Bf[((ntg * KT + kt) * 32 + lane) * 2];
                    #pragma unroll
                    for (int mt = 0; mt < 2; mt++)
                        mma16816(acc[mt][g][nt], Ah[mt], b.x, b.y);
                }
        }
        // epilogue: f16x2 activations (sigma(z) = 0.5 + 0.5*tanh(z/2); f*c = 0)
        #pragma unroll
        for (int mt = 0; mt < 2; mt++)
            #pragma unroll
            for (int nt = 0; nt < 2; nt++)
                #pragma unroll
                for (int i2 = 0; i2 < 2; i2++) {
                    int jb = (jq << 5) + (jci << 4) + (nt << 3) + ((lane & 3) << 1);
                    float ai0 = acc[mt][0][nt][2 * i2]     + bias[jb];
                    float ai1 = acc[mt][0][nt][2 * i2 + 1] + bias[jb + 1];
                    float ag0 = acc[mt][1][nt][2 * i2]     + bias[128 + jb];
                    float ag1 = acc[mt][1][nt][2 * i2 + 1] + bias[128 + jb + 1];
                    float ao0 = acc[mt][2][nt][2 * i2]     + bias[256 + jb];
                    float ao1 = acc[mt][2][nt][2 * i2 + 1] + bias[256 + jb + 1];
                    __half2 si = __hfma2(htanh2(__floats2half2_rn(0.5f * ai0, 0.5f * ai1)), H05, H05);
                    __half2 gg = htanh2(__floats2half2_rn(ag0, ag1));
                    __half2 so = __hfma2(htanh2(__floats2half2_rn(0.5f * ao0, 0.5f * ao1)), H05, H05);
                    __half2 tc = htanh2(__hmul2(si, gg));
                    __half2 h2 = __hmul2(so, tc);
                    int row = m0 + mt * 16 + (lane >> 2) + (i2 << 3);
                    *(uint32_t*)(smem + hOff + row * AS + jb * 2) = *(uint32_t*)&h2;
                }
    }
}

__global__ void __launch_bounds__(256, 2)
lstm_mma_kernel(const float* __restrict__ x,
                const float* __restrict__ bp, const float* __restrict__ bv,
                float* __restrict__ out)
{
    extern __shared__ char smem[];
    uint32_t sbase = smem_u32(smem);
    int tid = threadIdx.x;
    int lane = tid & 31;
    int warp = tid >> 5;
    int jq = warp & 3;               // col-quad (32 cols) owned by this warp
    int m0 = (warp >> 2) << 5;       // 32-row group (0 or 32)
    int r0 = blockIdx.x * TILE_M;

    // ---- stage biases ----
    float* bias_s = (float*)(smem + SM_BIAS);
    for (int i = tid; i < 384; i += 256) { bias_s[i] = g_b0[i]; bias_s[384 + i] = g_b1[i]; }

    // ---- stage x as fp16 into bufA (128B per row) ----
    {
        const float4* xg = (const float4*)(x + (size_t)r0 * 64);
        for (int it = tid; it < 64 * 16; it += 256) {
            int r = it >> 4, c4 = it & 15;
            float4 v = xg[r * 16 + c4];
            char* p = smem + SM_BUFA + r * AS + (c4 << 3);
            *(uint32_t*)p       = hpack(v.x, v.y);
            *(uint32_t*)(p + 4) = hpack(v.z, v.w);
        }
    }
    __syncthreads();

    gemm_layer<4>(smem, sbase, SM_BUFA, SM_BUFB, g_B0, bias_s,       m0, lane, jq);  // x -> h0
    __syncthreads();
    gemm_layer<8>(smem, sbase, SM_BUFB, SM_BUFA, g_B1, bias_s + 384, m0, lane, jq);  // h0 -> h1
    __syncthreads();

    // ---- heads: h1 @ [Wp;Wv]^T, N=24. col-quads 0..2 take one 8-col tile each ----
    if (jq < 3) {
        float acc[2][4];
        #pragma unroll
        for (int z = 0; z < 8; z++) ((float*)acc)[z] = 0.0f;

        #pragma unroll
        for (int kt = 0; kt < 8; kt++) {
            uint32_t Ah[2][4];
            #pragma unroll
            for (int mt = 0; mt < 2; mt++) {
                uint32_t a = sbase + SM_BUFA
                           + (uint32_t)(m0 + mt * 16 + (lane & 15)) * AS
                           + (uint32_t)(kt * 32 + (lane >> 4) * 16);
                ldmx4(Ah[mt], a);
            }
            uint2 b = *(const uint2*)&g_B2[(((jq << 3) + kt) * 32 + lane) * 2];
            #pragma unroll
            for (int mt = 0; mt < 2; mt++)
                mma16816(acc[mt], Ah[mt], b.x, b.y);
        }
        float bv0 = __ldg(bv);
        #pragma unroll
        for (int mt = 0; mt < 2; mt++)
            #pragma unroll
            for (int i2 = 0; i2 < 2; i2++) {
                int row = r0 + m0 + mt * 16 + (lane >> 2) + (i2 << 3);
                if (jq < 2) {     // policy cols jq*8 .. jq*8+7
                    int j0 = (jq << 3) + ((lane & 3) << 1);
                    float2 v;
                    v.x = acc[mt][2 * i2]     + __ldg(bp + j0);
                    v.y = acc[mt][2 * i2 + 1] + __ldg(bp + j0 + 1);
                    *(float2*)(out + (size_t)row * 16 + j0) = v;
                } else if ((lane & 3) == 0) {   // value = col 16 (tile 2, first pair, q=0)
                    out[(size_t)BATCH * 16 + row] = acc[mt][2 * i2] + bv0;
                }
            }
    }
}

extern "C" void kernel_launch(void* const* d_in, const int* in_sizes, int n_in,
                              void* d_out, int out_size)
{
    (void)in_sizes; (void)n_in; (void)out_size;
    const float* x    = (const float*)d_in[0];
    const float* Wih0 = (const float*)d_in[1];
    const float* bih0 = (const float*)d_in[3];
    const float* bhh0 = (const float*)d_in[4];
    const float* Wih1 = (const float*)d_in[5];
    const float* bih1 = (const float*)d_in[7];
    const float* bhh1 = (const float*)d_in[8];
    const float* Wp   = (const float*)d_in[9];
    const float* bp   = (const float*)d_in[10];
    const float* Wv   = (const float*)d_in[11];
    const float* bv   = (const float*)d_in[12];
    float* out = (float*)d_out;

    prep_kernel<<<64, 256>>>(Wih0, bih0, bhh0, Wih1, bih1, bhh1, Wp, Wv);

    cudaFuncSetAttribute(lstm_mma_kernel,
                         cudaFuncAttributeMaxDynamicSharedMemorySize, SMEM_TOTAL);
    lstm_mma_kernel<<<BATCH / TILE_M, 256, SMEM_TOTAL>>>(x, bp, bv, out);
}